// round 16
// baseline (speedup 1.0000x reference)
#include <cuda_runtime.h>
#include <cuda_fp16.h>
#include <cstdint>

#define Bn 4
#define Ln 1024
#define Un 1024
#define Hn 16
#define Dn 64
#define MREL 129
#define BHn 64
#define SCALE 0.125f
typedef __half hf;

// ---------------- static device scratch (no allocation) ----------------------
__device__ __align__(128) hf g_xh[Bn*Ln*Un];
__device__ __align__(128) hf g_wth[4*Un*Un];                 // W^T hi; wq|wk|wv|wo
__device__ __align__(128) hf g_ekh[Hn*MREL*Dn];              // [h,m,d]
__device__ __align__(128) hf g_evth[Hn*Dn*192];              // ev^T, pad 192
__device__ __align__(128) hf g_qh[Bn*Ln*Un];
__device__ __align__(128) hf g_kh[Bn*Ln*Un];
__device__ __align__(128) hf g_vth[BHn*Dn*Ln];               // [bh,d,l]
__device__ __align__(128) hf g_oh[Bn*Ln*Un];

// ---------------- helpers ----------------------------------------------------
__device__ __forceinline__ uint32_t smem_u32(const void* p){
    uint32_t a;
    asm("{ .reg .u64 t; cvta.to.shared.u64 t, %1; cvt.u32.u64 %0, t; }":"=r"(a):"l"(p));
    return a;
}
__device__ __forceinline__ void ldsm4(uint32_t* r, uint32_t a){
    asm volatile("ldmatrix.sync.aligned.m8n8.x4.shared.b16 {%0,%1,%2,%3}, [%4];"
        :"=r"(r[0]),"=r"(r[1]),"=r"(r[2]),"=r"(r[3]):"r"(a));
}
__device__ __forceinline__ void mma16816(float* d, const uint32_t* a, const uint32_t* b){
    asm volatile("mma.sync.aligned.m16n8k16.row.col.f32.f16.f16.f32 "
        "{%0,%1,%2,%3}, {%4,%5,%6,%7}, {%8,%9}, {%0,%1,%2,%3};"
        : "+f"(d[0]),"+f"(d[1]),"+f"(d[2]),"+f"(d[3])
        : "r"(a[0]),"r"(a[1]),"r"(a[2]),"r"(a[3]),"r"(b[0]),"r"(b[1]));
}
__device__ __forceinline__ void cpa(uint32_t dst, const void* src, uint32_t sz){
    asm volatile("cp.async.cg.shared.global [%0], [%1], 16, %2;"::"r"(dst),"l"(src),"r"(sz));
}

// ---------------- generic 1-term fp16 warp-MMA GEMM --------------------------
// K-chunks of 64, 3-stage cp.async pipeline, single __syncthreads per chunk.
// MODE 5: fused QKV (N=3072; sel 0->q, 1->k, 2->V transposed to g_vth)
// MODE 4: out proj + bias -> fp32
template<int NT,int MODE,int NCH>
__global__ void __launch_bounds__(256,2) gemm_mma(
    const hf* __restrict__ A0h,
    const hf* __restrict__ B0h,
    float* __restrict__ cf, hf* __restrict__ ch,
    hf* __restrict__ ch2,
    const float* __restrict__ bias)
{
    constexpr int WN = NT/2;
    constexpr int NS = WN/8;
    constexpr int ABYT = 128*144;        // one 128x64 fp16 array, pitch 144B
    constexpr int BUF  = 2*ABYT;         // A | B per stage
    extern __shared__ char smc[];
    const uint32_t S = smem_u32(smc);
    const int t = threadIdx.x, lane = t&31, w = t>>5;
    const int wm = w>>1, wn = w&1;

    const int m0 = blockIdx.y*128, n0 = blockIdx.x*NT;
    const hf *Ah = A0h+(size_t)m0*Un;
    const hf *Bh = B0h+(size_t)n0*Un;

    const int rA = lane&15,               kA = (lane>>4)*8;
    const int rB = (lane&7)+((lane>>4)<<3), kB = ((lane>>3)&1)*8;
    uint32_t aoff[2], boff[NS/2 > 0 ? NS/2 : 1];
    #pragma unroll
    for (int ms=0; ms<2; ms++) aoff[ms] = (uint32_t)((wm*32+ms*16+rA)*144 + kA*2);
    #pragma unroll
    for (int p4=0; p4<NS/2; p4++) boff[p4] = (uint32_t)(ABYT + (wn*WN+p4*16+rB)*144 + kB*2);

    auto load_chunk = [&](int c, int p){
        const hf *gah=Ah+c*64, *gbh=Bh+c*64;
        uint32_t sbase = S + p*BUF;
        #pragma unroll
        for (int i=0;i<8;i++){
            int e = t + i*256;
            int arr = e >> 10;           // 0:A 1:B
            int e2 = e & 1023;
            int r  = e2 >> 3;
            int sg = e2 & 7;
            const hf* src = (arr==0 ? gah : gbh) + (size_t)r*Un + sg*8;
            cpa(sbase + (uint32_t)(arr*ABYT + r*144 + sg*16), src, 16);
        }
        asm volatile("cp.async.commit_group;" ::: "memory");
    };

    float acc[2][NS][4];
    #pragma unroll
    for (int ms=0;ms<2;ms++)
        #pragma unroll
        for (int ns=0;ns<NS;ns++)
            #pragma unroll
            for (int k=0;k<4;k++) acc[ms][ns][k] = 0.f;

    load_chunk(0, 0);
    load_chunk(1, 1);
    int st = 2;                          // next stage slot to fill
    for (int c = 0; c < NCH; c++){
        if (c+1 < NCH){
            asm volatile("cp.async.wait_group 1;" ::: "memory");
        } else {
            asm volatile("cp.async.wait_group 0;" ::: "memory");
        }
        __syncthreads();
        if (c+2 < NCH){
            load_chunk(c+2, st);
            st = (st+1==3)?0:st+1;
        }
        uint32_t base = S + (uint32_t)(c%3)*BUF;
        #pragma unroll
        for (int k16=0;k16<4;k16++){
            uint32_t ah2[2][4];
            #pragma unroll
            for (int ms=0;ms<2;ms++)
                ldsm4(ah2[ms], base + aoff[ms] + k16*32);
            #pragma unroll
            for (int p4=0;p4<NS/2;p4++){
                uint32_t bh4[4];
                ldsm4(bh4, base + boff[p4] + k16*32);
                #pragma unroll
                for (int ms=0;ms<2;ms++){
                    mma16816(acc[ms][2*p4],   ah2[ms], bh4);
                    mma16816(acc[ms][2*p4+1], ah2[ms], bh4+2);
                }
            }
        }
    }

    const int lr = lane>>2, lc = (lane&3)<<1;
    const int sel = (MODE==5) ? (n0>>10) : 0;

    if (MODE==5 && sel==2){
        // ---- V path: stage tile to smem, emit transposed [bh,d,l] ----
        __syncthreads();                       // all warps done with ldsm reads
        hf* vs = (hf*)smc;                     // pitch 134 halves
        #pragma unroll
        for (int ms=0;ms<2;ms++){
            #pragma unroll
            for (int ns=0;ns<NS;ns++){
                const int rt = wm*32 + ms*16 + lr;
                const int ct = wn*WN + ns*8 + lc;
                float* a = acc[ms][ns];
                *(__half2*)(vs + rt*134 + ct)     = __floats2half2_rn(a[0], a[1]);
                *(__half2*)(vs + (rt+8)*134 + ct) = __floats2half2_rn(a[2], a[3]);
            }
        }
        __syncthreads();
        const int nc0 = n0 & 1023;
        for (int idx=t; idx<128*64; idx+=256){
            int ul = idx>>6;
            int lp = (idx&63)<<1;
            int u  = nc0 + ul;
            int hh = u>>6, dd = u&63;
            int gr = m0 + lp;
            int bb = gr>>10, ll = gr&1023;
            __half2 v2;
            v2.x = vs[lp*134+ul]; v2.y = vs[(lp+1)*134+ul];
            *(__half2*)(g_vth + ((((size_t)((bb<<4)+hh)<<6)+dd)<<10) + ll) = v2;
        }
        return;
    }

    #pragma unroll
    for (int ms=0;ms<2;ms++){
        #pragma unroll
        for (int ns=0;ns<NS;ns++){
            const int rt = wm*32 + ms*16 + lr;
            const int ct = wn*WN + ns*8 + lc;
            float* a = acc[ms][ns];
            if (MODE==5){
                int ncol = (n0 & 1023) + ct;
                size_t d0 = (size_t)(m0+rt)*Un + ncol;
                hf* o2 = sel==0? ch : ch2;
                *(__half2*)(o2+d0) = __floats2half2_rn(a[0], a[1]);
                *(__half2*)(o2+d0+(size_t)8*Un) = __floats2half2_rn(a[2], a[3]);
            } else {
                const int R = m0+rt, C = n0+ct;
                float2 v;
                v.x = a[0]+bias[C]; v.y = a[1]+bias[C+1];
                *(float2*)(cf+(size_t)R*Un+C) = v;
                v.x = a[2]+bias[C]; v.y = a[3]+bias[C+1];
                *(float2*)(cf+(size_t)(R+8)*Un+C) = v;
            }
        }
    }
}

// ---------------- fused flash attention + relative positions -----------------
#define PIT 144
#define AS_K    0
#define AS_V    9216
#define AS_PH   18432
#define AS_WR   36864       // fp16 128 x 132; aliased as Q staging during prologue
#define AS_QM   70656       // fp16 128 x 132 (computed in-kernel: Q . ek^T)
#define AS_MSK  104448      // fp32 1024, premultiplied by -1e9
#define AS_RM   108544      // fp32 128 : final row max
#define AS_TOT  109056

__global__ void __launch_bounds__(256,2) attn_fused(const float* __restrict__ maskg)
{
    extern __shared__ char smc[];
    const uint32_t S = smem_u32(smc);
    hf* swrh = (hf*)(smc + AS_WR);
    hf* sqm = (hf*)(smc + AS_QM);
    float* smk = (float*)(smc + AS_MSK);
    float* srm = (float*)(smc + AS_RM);
    const int t = threadIdx.x, lane = t&31, w = t>>5;
    const int bh = blockIdx.y, b = bh>>4, h = bh&15;
    const int i0 = blockIdx.x<<7;

    // Q tile 128x64 staged into WR region (not live yet)
    #pragma unroll
    for (int i=0;i<4;i++){
        int v = t + (i<<8);
        int r = v>>3, sg = v&7;
        const hf* src = g_qh + (((size_t)((b<<10)+i0+r))<<10) + (h<<6) + sg*8;
        cpa(S + AS_WR + r*PIT + sg*16, src, 16);
    }
    asm volatile("cp.async.commit_group;":::"memory");

    auto ldK = [&](int c){
        const int j0 = c<<6;
        #pragma unroll
        for (int i=0;i<2;i++){
            int e = t + (i<<8);
            int row = e>>3, sg = e&7;
            const hf* src = g_kh + (((size_t)((b<<10)+j0+row))<<10) + (h<<6) + sg*8;
            cpa(S + AS_K + row*PIT + sg*16, src, 16);
        }
        asm volatile("cp.async.commit_group;":::"memory");
    };
    auto ldV = [&](int c){
        const int j0 = c<<6;
        #pragma unroll
        for (int i=0;i<2;i++){
            int e = t + (i<<8);
            int row = e>>3, sg = e&7;
            const hf* src = g_vth + (((size_t)((bh<<6)+row))<<10) + j0 + sg*8;
            cpa(S + AS_V + row*PIT + sg*16, src, 16);
        }
        asm volatile("cp.async.commit_group;":::"memory");
    };
    auto ldEk = [&](int mc){
        #pragma unroll
        for (int i=0;i<2;i++){
            int e = t + (i<<8);
            int row = e>>3, sg = e&7;
            int m = (mc<<6) + row;
            int rs = m < MREL ? m : 0;
            const hf* src = g_ekh + ((size_t)h*MREL + rs)*Dn + sg*8;
            cpa(S + AS_K + row*PIT + sg*16, src, 16);
        }
        asm volatile("cp.async.commit_group;":::"memory");
    };
    auto ldEv = [&](int mc, uint32_t slot){
        #pragma unroll
        for (int i=0;i<2;i++){
            int e = t + (i<<8);
            int row = e>>3, sg = e&7;
            const hf* src = g_evth + (size_t)h*Dn*192 + (size_t)row*192 + (mc<<6) + sg*8;
            cpa(S + slot + row*PIT + sg*16, src, 16);
        }
        asm volatile("cp.async.commit_group;":::"memory");
    };

    for (int v=t; v<1024; v+=256) smk[v] = maskg[(b<<10)+v] * -1e9f;

    const int rA = lane&15, kA = (lane>>4)<<3;
    const int rB = (lane&7)+((lane>>4)<<3), kB = ((lane>>3)&1)<<3;
    const uint32_t aQ  = S + AS_WR + (16*w + rA)*PIT + kA*2;
    const uint32_t aPh = S + AS_PH + (16*w + rA)*PIT + kA*2;
    const uint32_t kK = S + AS_K;
    const uint32_t kV = S + AS_V;
    const int r0l = (w<<4) + (lane>>2), r1l = r0l + 8;
    const int cl0 = (lane&3)<<1;

    // ---- prologue: sqm = Q . ek^T ----
    asm volatile("cp.async.wait_group 0;":::"memory");
    __syncthreads();
    for (int mc=0; mc<3; mc++){
        ldEk(mc);
        asm volatile("cp.async.wait_group 0;":::"memory");
        __syncthreads();
        float s[8][4] = {};
        #pragma unroll
        for (int k16=0;k16<4;k16++){
            uint32_t ah4[4];
            ldsm4(ah4, aQ + k16*32);
            #pragma unroll
            for (int p4=0;p4<4;p4++){
                uint32_t bh4[4];
                ldsm4(bh4, kK + (p4*16 + rB)*PIT + kB*2 + k16*32);
                mma16816(s[2*p4],   ah4, bh4);
                mma16816(s[2*p4+1], ah4, bh4+2);
            }
        }
        #pragma unroll
        for (int ns=0;ns<8;ns++){
            int m = (mc<<6) + (ns<<3) + cl0;
            if (m <= 130){
                *(__half2*)(sqm + r0l*132 + m) = __floats2half2_rn(s[ns][0], s[ns][1]);
                *(__half2*)(sqm + r1l*132 + m) = __floats2half2_rn(s[ns][2], s[ns][3]);
            }
        }
        __syncthreads();
    }

    // ---- hoist Q fragments to registers; reuse staging smem as WR ----
    uint32_t q4[4][4];
    #pragma unroll
    for (int k16=0;k16<4;k16++) ldsm4(q4[k16], aQ + k16*32);
    __syncthreads();
    {
        const hf ninf = __float2half(-60000.f);
        for (int v=t; v<128*132; v+=256) swrh[v] = ninf;
    }
    __syncthreads();
    ldK(0); ldV(0);

    float o[8][4] = {};
    float M0 = -1e30f, M1 = -1e30f, L0 = 0.f, L1 = 0.f;
    float elo0 = 0.f, ehi0 = 0.f, elo1 = 0.f, ehi1 = 0.f;

    for (int c=0; c<16; c++){
        asm volatile("cp.async.wait_group 0;":::"memory");
        __syncthreads();

        // ---- S = Q K^T ----
        float s[8][4] = {};
        #pragma unroll
        for (int k16=0;k16<4;k16++){
            #pragma unroll
            for (int p4=0;p4<4;p4++){
                uint32_t bh4[4];
                ldsm4(bh4, kK + (p4*16 + rB)*PIT + kB*2 + k16*32);
                mma16816(s[2*p4],   q4[k16], bh4);
                mma16816(s[2*p4+1], q4[k16], bh4+2);
            }
        }
        __syncthreads();
        if (c+1 < 16) ldK(c+1);

        const int jbase = c<<6;
        const bool flo = (jbase <= i0 - 127);
        const bool fhi = (jbase >= i0 + 191);
        float mx0 = -1e30f, mx1 = -1e30f;
        float sum0 = 0.f, sum1 = 0.f;

        if (flo || fhi){
            const int qcol = flo ? 0 : 128;
            const float a0 = __half2float(sqm[r0l*132+qcol])*SCALE;
            const float a1 = __half2float(sqm[r1l*132+qcol])*SCALE;
            #pragma unroll
            for (int ns=0;ns<8;ns++){
                int jl = (ns<<3) + cl0;
                float mk0 = smk[jbase+jl], mk1 = smk[jbase+jl+1];
                s[ns][0] = s[ns][0]*SCALE + a0 + mk0;
                s[ns][1] = s[ns][1]*SCALE + a0 + mk1;
                s[ns][2] = s[ns][2]*SCALE + a1 + mk0;
                s[ns][3] = s[ns][3]*SCALE + a1 + mk1;
                mx0 = fmaxf(mx0, fmaxf(s[ns][0], s[ns][1]));
                mx1 = fmaxf(mx1, fmaxf(s[ns][2], s[ns][3]));
            }
            mx0 = fmaxf(mx0, __shfl_xor_sync(0xffffffffu, mx0, 1));
            mx0 = fmaxf(mx0, __shfl_xor_sync(0xffffffffu, mx0, 2));
            mx1 = fmaxf(mx1, __shfl_xor_sync(0xffffffffu, mx1, 1));
            mx1 = fmaxf(mx1, __shfl_xor_sync(0xffffffffu, mx1, 2));
            const float nM0 = fmaxf(M0, mx0), nM1 = fmaxf(M1, mx1);
            const float f0 = __expf(M0 - nM0), f1 = __expf(M1 - nM1);
            M0 = nM0; M1 = nM1;
            #pragma unroll
            for (int ns=0;ns<8;ns++){
                int jl = (ns<<3) + cl0;
                float p00=__expf(s[ns][0]-nM0), p01=__expf(s[ns][1]-nM0);
                float p10=__expf(s[ns][2]-nM1), p11=__expf(s[ns][3]-nM1);
                sum0 += p00+p01; sum1 += p10+p11;
                *(__half2*)(smc + AS_PH + r0l*PIT + jl*2) = __floats2half2_rn(p00, p01);
                *(__half2*)(smc + AS_PH + r1l*PIT + jl*2) = __floats2half2_rn(p10, p11);
            }
            #pragma unroll
            for (int ns=0;ns<8;ns++){ o[ns][0]*=f0; o[ns][1]*=f0; o[ns][2]*=f1; o[ns][3]*=f1; }
            L0 = L0*f0 + sum0;  L1 = L1*f1 + sum1;
            if (flo){ elo0 = elo0*f0 + sum0; elo1 = elo1*f1 + sum1;
                      ehi0 *= f0;            ehi1 *= f1; }
            else    { ehi0 = ehi0*f0 + sum0; ehi1 = ehi1*f1 + sum1;
                      elo0 *= f0;            elo1 *= f1; }
        } else {
            #pragma unroll
            for (int ns=0;ns<8;ns++){
                int jl = (ns<<3) + cl0;
                int jg0 = jbase + jl, jg1 = jg0 + 1;
                int d00 = jg0-(i0+r0l); int c00 = d00<-64?-64:(d00>64?64:d00);
                int d01 = jg1-(i0+r0l); int c01 = d01<-64?-64:(d01>64?64:d01);
                int d10 = jg0-(i0+r1l); int c10 = d10<-64?-64:(d10>64?64:d10);
                int d11 = jg1-(i0+r1l); int c11 = d11<-64?-64:(d11>64?64:d11);
                s[ns][0] = (s[ns][0] + __half2float(sqm[r0l*132+c00+64]))*SCALE + smk[jg0];
                s[ns][1] = (s[ns][1] + __half2float(sqm[r0l*132+c01+64]))*SCALE + smk[jg1];
                s[ns][2] = (s[ns][2] + __half2float(sqm[r1l*132+c10+64]))*SCALE + smk[jg0];
                s[ns][3] = (s[ns][3] + __half2float(sqm[r1l*132+c11+64]))*SCALE + smk[jg1];
                if (d00>-64 && d00<64) swrh[r0l*132+d00+64] = __float2half(s[ns][0]);
                if (d01>-64 && d01<64) swrh[r0l*132+d01+64] = __float2half(s[ns][1]);
                if (d10>-64 && d10<64) swrh[r1l*132+d10+64] = __float2half(s[ns][2]);
                if (d11>-64 && d11<64) swrh[r1l*132+d11+64] = __float2half(s[ns][3]);
                mx0 = fmaxf(mx0, fmaxf(s[ns][0], s[ns][1]));
                mx1 = fmaxf(mx1, fmaxf(s[ns][2], s[ns][3]));
            }
            mx0 = fmaxf(mx0, __shfl_xor_sync(0xffffffffu, mx0, 1));
            mx0 = fmaxf(mx0, __shfl_xor_sync(0xffffffffu, mx0, 2));
            mx1 = fmaxf(mx1, __shfl_xor_sync(0xffffffffu, mx1, 1));
            mx1 = fmaxf(mx1, __shfl_xor_sync(0xffffffffu, mx1, 2));
            const float nM0 = fmaxf(M0, mx0), nM1 = fmaxf(M1, mx1);
            const float f0 = __expf(M0 - nM0), f1 = __expf(M1 - nM1);
            M0 = nM0; M1 = nM1;

            float ce0 = 0.f, ch0 = 0.f, ce1 = 0.f, ch1 = 0.f;
            #pragma unroll
            for (int ns=0;ns<8;ns++){
                int jl = (ns<<3) + cl0;
                int jg0 = jbase + jl, jg1 = jg0 + 1;
                int d00 = jg0-(i0+r0l), d01 = jg1-(i0+r0l);
                int d10 = jg0-(i0+r1l), d11 = jg1-(i0+r1l);
                float p00=__expf(s[ns][0]-nM0), p01=__expf(s[ns][1]-nM0);
                float p10=__expf(s[ns][2]-nM1), p11=__expf(s[ns][3]-nM1);
                sum0 += p00+p01; sum1 += p10+p11;
                if (d00<=-64) ce0+=p00; else if (d00>=64) ch0+=p00;
                if (d01<=-64) ce0+=p01; else if (d01>=64) ch0+=p01;
                if (d10<=-64) ce1+=p10; else if (d10>=64) ch1+=p10;
                if (d11<=-64) ce1+=p11; else if (d11>=64) ch1+=p11;
                *(__half2*)(smc + AS_PH + r0l*PIT + jl*2) = __floats2half2_rn(p00, p01);
                *(__half2*)(smc + AS_PH + r1l*PIT + jl*2) = __floats2half2_rn(p10, p11);
            }
            #pragma unroll
            for (int ns=0;ns<8;ns++){ o[ns][0]*=f0; o[ns][1]*=f0; o[ns][2]*=f1; o[ns][3]*=f1; }
            L0 = L0*f0 + sum0;  L1 = L1*f1 + sum1;
            elo0 = elo0*f0 + ce0; ehi0 = ehi0*f0 + ch0;
            elo1 = elo1*f1 + ce1; ehi1 = ehi1*f1 + ch1;
        }
        __syncwarp();

        // ---- O += P V^T ----
        #pragma unroll
        for (int k16=0;k16<4;k16++){
            uint32_t ph4[4];
            ldsm4(ph4, aPh + k16*32);
            #pragma unroll
            for (int p4=0;p4<4;p4++){
                uint32_t vh4[4];
                ldsm4(vh4, kV + (p4*16 + rB)*PIT + kB*2 + k16*32);
                mma16816(o[2*p4],   ph4, vh4);
                mma16816(o[2*p4+1], ph4, vh4+2);
            }
        }
        __syncthreads();
        if (c+1 < 16) ldV(c+1);
    }

    // finalize row state
    elo0 += __shfl_xor_sync(0xffffffffu, elo0, 1); elo0 += __shfl_xor_sync(0xffffffffu, elo0, 2);
    ehi0 += __shfl_xor_sync(0xffffffffu, ehi0, 1); ehi0 += __shfl_xor_sync(0xffffffffu, ehi0, 2);
    elo1 += __shfl_xor_sync(0xffffffffu, elo1, 1); elo1 += __shfl_xor_sync(0xffffffffu, elo1, 2);
    ehi1 += __shfl_xor_sync(0xffffffffu, ehi1, 1); ehi1 += __shfl_xor_sync(0xffffffffu, ehi1, 2);
    L0 += __shfl_xor_sync(0xffffffffu, L0, 1); L0 += __shfl_xor_sync(0xffffffffu, L0, 2);
    L1 += __shfl_xor_sync(0xffffffffu, L1, 1); L1 += __shfl_xor_sync(0xffffffffu, L1, 2);
    if ((lane&3)==0){
        swrh[r0l*132+0]   = __float2half(elo0);
        swrh[r0l*132+128] = __float2half(ehi0);
        swrh[r1l*132+0]   = __float2half(elo1);
        swrh[r1l*132+128] = __float2half(ehi1);
        srm[r0l] = M0; srm[r1l] = M1;
    }
    __syncthreads();

    // ---- O += wr @ ev^T (3 chunks, double-buffered across K/V slots) ----
    ldEv(0, AS_V);
    for (int mc=0; mc<3; mc++){
        for (int idx=t; idx<128*64; idx+=256){
            int r = idx>>6, c2 = idx&63;
            int col = (mc<<6) + c2;
            float v;
            if (col==0 || col==128) v = __half2float(swrh[r*132+col]);
            else if (col < MREL)    v = __expf(__half2float(swrh[r*132+col]) - srm[r]);
            else                    v = 0.f;
            *(hf*)(smc + AS_PH + r*PIT + c2*2) = __float2half(v);
        }
        asm volatile("cp.async.wait_group 0;":::"memory");
        __syncthreads();
        if (mc < 2) ldEv(mc+1, (mc&1)? AS_V : AS_K);
        const uint32_t slot = (mc&1)? kK : kV;
        #pragma unroll
        for (int k16=0;k16<4;k16++){
            uint32_t ph4[4];
            ldsm4(ph4, aPh + k16*32);
            #pragma unroll
            for (int p4=0;p4<4;p4++){
                uint32_t vh4[4];
                ldsm4(vh4, slot + (p4*16 + rB)*PIT + kB*2 + k16*32);
                mma16816(o[2*p4],   ph4, vh4);
                mma16816(o[2*p4+1], ph4, vh4+2);
            }
        }
        __syncthreads();
    }

    // ---- normalize + emit ----
    const float inv0 = 1.0f/L0, inv1 = 1.0f/L1;
    #pragma unroll
    for (int ns=0;ns<8;ns++){
        int ct = (ns<<3) + cl0;
        size_t d0 = ((size_t)((b<<10)+i0+r0l)<<10) + (h<<6) + ct;
        size_t d1 = ((size_t)((b<<10)+i0+r1l)<<10) + (h<<6) + ct;
        *(__half2*)(g_oh+d0) = __floats2half2_rn(o[ns][0]*inv0, o[ns][1]*inv0);
        *(__half2*)(g_oh+d1) = __floats2half2_rn(o[ns][2]*inv1, o[ns][3]*inv1);
    }
}

// ---------------- prep kernels ----------------------------------------------
__global__ void conv_h(const float* __restrict__ x, hf* __restrict__ h, int n4){
    int i = blockIdx.x*256 + threadIdx.x;
    if (i >= n4) return;
    float4 v = ((const float4*)x)[i];
    hf hb[4];
    hb[0]=__float2half(v.x); hb[1]=__float2half(v.y);
    hb[2]=__float2half(v.z); hb[3]=__float2half(v.w);
    ((uint2*)h)[i] = *(uint2*)hb;
}

__global__ void convT_all(const float* __restrict__ w0, const float* __restrict__ w1,
                          const float* __restrict__ w2, const float* __restrict__ w3,
                          hf* __restrict__ ohb){
    __shared__ float tl[32][33];
    const int z = blockIdx.z;
    const float* w = z==0? w0 : (z==1? w1 : (z==2? w2 : w3));
    hf* oh = ohb + (size_t)z*Un*Un;
    const int n0 = blockIdx.x*32, k0 = blockIdx.y*32;
    const int tx = threadIdx.x, ty = threadIdx.y;
    for (int yy = 0; yy < 32; yy += 8)
        tl[ty+yy][tx] = w[(size_t)(k0+ty+yy)*Un + n0+tx];
    __syncthreads();
    for (int yy = 0; yy < 32; yy += 8)
        oh[(size_t)(n0+ty+yy)*Un + k0+tx] = __float2half(tl[tx][ty+yy]);
}

__global__ void prep_e(const float* __restrict__ ek, const float* __restrict__ ev){
    const int hh = blockIdx.x;
    if (blockIdx.y == 0){
        for (int v = threadIdx.x; v < Dn*192; v += 256){
            int d = v/192, m = v%192;
            float f = (m < MREL) ? ev[(size_t)hh*MREL*Dn + (size_t)m*Dn + d] : 0.f;
            g_evth[(size_t)hh*Dn*192 + v] = __float2half(f);
        }
    } else {
        for (int v = threadIdx.x; v < MREL*Dn; v += 256)
            g_ekh[(size_t)hh*MREL*Dn + v] = __float2half(ek[(size_t)hh*MREL*Dn + v]);
    }
}

// -----------------------------------------------------------------------------
#define SMEMG (3*2*128*144)    // 110592 (3-stage pipeline)

extern "C" void kernel_launch(void* const* d_in, const int* in_sizes, int n_in,
                              void* d_out, int out_size)
{
    const float* x    = (const float*)d_in[0];
    const float* mask = (const float*)d_in[1];
    const float* wq   = (const float*)d_in[2];
    const float* wk   = (const float*)d_in[3];
    const float* wv   = (const float*)d_in[4];
    const float* wo   = (const float*)d_in[5];
    const float* bo   = (const float*)d_in[6];
    const float* ek   = (const float*)d_in[7];
    const float* ev   = (const float*)d_in[8];
    float* out = (float*)d_out;

    hf *xh,*wth,*qh,*kh,*oh;
    cudaGetSymbolAddress((void**)&xh, g_xh);
    cudaGetSymbolAddress((void**)&wth, g_wth);
    cudaGetSymbolAddress((void**)&qh, g_qh);
    cudaGetSymbolAddress((void**)&kh, g_kh);
    cudaGetSymbolAddress((void**)&oh, g_oh);

    cudaFuncSetAttribute(gemm_mma<128,5,16>, cudaFuncAttributeMaxDynamicSharedMemorySize, SMEMG);
    cudaFuncSetAttribute(gemm_mma<128,4,16>, cudaFuncAttributeMaxDynamicSharedMemorySize, SMEMG);
    cudaFuncSetAttribute(attn_fused, cudaFuncAttributeMaxDynamicSharedMemorySize, AS_TOT);

    // prep
    conv_h<<<(Bn*Ln*Un/4+255)/256, 256>>>(x, xh, Bn*Ln*Un/4);
    prep_e<<<dim3(Hn,2), 256>>>(ek, ev);
    convT_all<<<dim3(32,32,4), dim3(32,8)>>>(wq, wk, wv, wo, wth);

    // fused Q|K|V projection (K-chunks of 64, 3-stage pipeline)
    gemm_mma<128,5,16><<<dim3(24, (Bn*Ln)/128, 1),256,SMEMG>>>(
        xh, wth, 0, qh, kh, 0);

    // fused attention (qm + logits + softmax + rel-value + AV), 2 CTA/SM
    attn_fused<<<dim3(Ln/128, BHn), 256, AS_TOT>>>(mask);

    // out = O @ Wo^T + bo
    gemm_mma<128,4,16><<<dim3(8, (Bn*Ln)/128, 1),256,SMEMG>>>(
        oh, wth+3*Un*Un, out, 0, 0, bo);
}

// round 17
// speedup vs baseline: 1.0166x; 1.0166x over previous
#include <cuda_runtime.h>
#include <cuda_fp16.h>
#include <cstdint>

#define Bn 4
#define Ln 1024
#define Un 1024
#define Hn 16
#define Dn 64
#define MREL 129
#define BHn 64
#define SCALE 0.125f
typedef __half hf;

// ---------------- static device scratch (no allocation) ----------------------
__device__ __align__(128) hf g_xh[Bn*Ln*Un];
__device__ __align__(128) hf g_wth[4*Un*Un];                 // W^T hi; wq|wk|wv|wo
__device__ __align__(128) hf g_ekh[Hn*MREL*Dn];              // [h,m,d]
__device__ __align__(128) hf g_evth[Hn*Dn*192];              // ev^T, pad 192
__device__ __align__(128) hf g_qh[Bn*Ln*Un];
__device__ __align__(128) hf g_kh[Bn*Ln*Un];
__device__ __align__(128) hf g_vth[BHn*Dn*Ln];               // [bh,d,l]
__device__ __align__(128) hf g_oh[Bn*Ln*Un];

// ---------------- helpers ----------------------------------------------------
__device__ __forceinline__ uint32_t smem_u32(const void* p){
    uint32_t a;
    asm("{ .reg .u64 t; cvta.to.shared.u64 t, %1; cvt.u32.u64 %0, t; }":"=r"(a):"l"(p));
    return a;
}
__device__ __forceinline__ void ldsm4(uint32_t* r, uint32_t a){
    asm volatile("ldmatrix.sync.aligned.m8n8.x4.shared.b16 {%0,%1,%2,%3}, [%4];"
        :"=r"(r[0]),"=r"(r[1]),"=r"(r[2]),"=r"(r[3]):"r"(a));
}
__device__ __forceinline__ void mma16816(float* d, const uint32_t* a, const uint32_t* b){
    asm volatile("mma.sync.aligned.m16n8k16.row.col.f32.f16.f16.f32 "
        "{%0,%1,%2,%3}, {%4,%5,%6,%7}, {%8,%9}, {%0,%1,%2,%3};"
        : "+f"(d[0]),"+f"(d[1]),"+f"(d[2]),"+f"(d[3])
        : "r"(a[0]),"r"(a[1]),"r"(a[2]),"r"(a[3]),"r"(b[0]),"r"(b[1]));
}
__device__ __forceinline__ void cpa(uint32_t dst, const void* src, uint32_t sz){
    asm volatile("cp.async.cg.shared.global [%0], [%1], 16, %2;"::"r"(dst),"l"(src),"r"(sz));
}

// ---------------- generic 1-term fp16 warp-MMA GEMM --------------------------
// K-chunks of 64, 2-stage, single __syncthreads per chunk. (R15 measured-best)
// MODE 5: fused QKV (N=3072; sel 0->q, 1->k, 2->V transposed to g_vth)
// MODE 4: out proj + bias -> fp32
template<int NT,int MODE,int NCH>
__global__ void __launch_bounds__(256,2) gemm_mma(
    const hf* __restrict__ A0h,
    const hf* __restrict__ B0h,
    float* __restrict__ cf, hf* __restrict__ ch,
    hf* __restrict__ ch2,
    const float* __restrict__ bias)
{
    constexpr int WN = NT/2;
    constexpr int NS = WN/8;
    constexpr int ABYT = 128*144;        // one 128x64 fp16 array, pitch 144B
    constexpr int BUF  = 2*ABYT;         // A | B per stage
    extern __shared__ char smc[];
    const uint32_t S = smem_u32(smc);
    const int t = threadIdx.x, lane = t&31, w = t>>5;
    const int wm = w>>1, wn = w&1;

    const int m0 = blockIdx.y*128, n0 = blockIdx.x*NT;
    const hf *Ah = A0h+(size_t)m0*Un;
    const hf *Bh = B0h+(size_t)n0*Un;

    const int rA = lane&15,               kA = (lane>>4)*8;
    const int rB = (lane&7)+((lane>>4)<<3), kB = ((lane>>3)&1)*8;
    uint32_t aoff[2], boff[NS/2 > 0 ? NS/2 : 1];
    #pragma unroll
    for (int ms=0; ms<2; ms++) aoff[ms] = (uint32_t)((wm*32+ms*16+rA)*144 + kA*2);
    #pragma unroll
    for (int p4=0; p4<NS/2; p4++) boff[p4] = (uint32_t)(ABYT + (wn*WN+p4*16+rB)*144 + kB*2);

    auto load_chunk = [&](int c, int p){
        const hf *gah=Ah+c*64, *gbh=Bh+c*64;
        uint32_t sbase = S + p*BUF;
        #pragma unroll
        for (int i=0;i<8;i++){
            int e = t + i*256;
            int arr = e >> 10;           // 0:A 1:B
            int e2 = e & 1023;
            int r  = e2 >> 3;
            int sg = e2 & 7;
            const hf* src = (arr==0 ? gah : gbh) + (size_t)r*Un + sg*8;
            cpa(sbase + (uint32_t)(arr*ABYT + r*144 + sg*16), src, 16);
        }
        asm volatile("cp.async.commit_group;" ::: "memory");
    };

    float acc[2][NS][4];
    #pragma unroll
    for (int ms=0;ms<2;ms++)
        #pragma unroll
        for (int ns=0;ns<NS;ns++)
            #pragma unroll
            for (int k=0;k<4;k++) acc[ms][ns][k] = 0.f;

    load_chunk(0, 0);
    for (int c = 0; c < NCH; c++){
        asm volatile("cp.async.wait_group 0;" ::: "memory");
        __syncthreads();
        if (c+1 < NCH) load_chunk(c+1, (c+1)&1);
        uint32_t base = S + (c&1)*BUF;
        #pragma unroll
        for (int k16=0;k16<4;k16++){
            uint32_t ah2[2][4];
            #pragma unroll
            for (int ms=0;ms<2;ms++)
                ldsm4(ah2[ms], base + aoff[ms] + k16*32);
            #pragma unroll
            for (int p4=0;p4<NS/2;p4++){
                uint32_t bh4[4];
                ldsm4(bh4, base + boff[p4] + k16*32);
                #pragma unroll
                for (int ms=0;ms<2;ms++){
                    mma16816(acc[ms][2*p4],   ah2[ms], bh4);
                    mma16816(acc[ms][2*p4+1], ah2[ms], bh4+2);
                }
            }
        }
    }

    const int lr = lane>>2, lc = (lane&3)<<1;
    const int sel = (MODE==5) ? (n0>>10) : 0;

    if (MODE==5 && sel==2){
        // ---- V path: stage tile to smem, emit transposed [bh,d,l] ----
        __syncthreads();
        hf* vs = (hf*)smc;                     // pitch 134 halves
        #pragma unroll
        for (int ms=0;ms<2;ms++){
            #pragma unroll
            for (int ns=0;ns<NS;ns++){
                const int rt = wm*32 + ms*16 + lr;
                const int ct = wn*WN + ns*8 + lc;
                float* a = acc[ms][ns];
                *(__half2*)(vs + rt*134 + ct)     = __floats2half2_rn(a[0], a[1]);
                *(__half2*)(vs + (rt+8)*134 + ct) = __floats2half2_rn(a[2], a[3]);
            }
        }
        __syncthreads();
        const int nc0 = n0 & 1023;
        for (int idx=t; idx<128*64; idx+=256){
            int ul = idx>>6;
            int lp = (idx&63)<<1;
            int u  = nc0 + ul;
            int hh = u>>6, dd = u&63;
            int gr = m0 + lp;
            int bb = gr>>10, ll = gr&1023;
            __half2 v2;
            v2.x = vs[lp*134+ul]; v2.y = vs[(lp+1)*134+ul];
            *(__half2*)(g_vth + ((((size_t)((bb<<4)+hh)<<6)+dd)<<10) + ll) = v2;
        }
        return;
    }

    #pragma unroll
    for (int ms=0;ms<2;ms++){
        #pragma unroll
        for (int ns=0;ns<NS;ns++){
            const int rt = wm*32 + ms*16 + lr;
            const int ct = wn*WN + ns*8 + lc;
            float* a = acc[ms][ns];
            if (MODE==5){
                int ncol = (n0 & 1023) + ct;
                size_t d0 = (size_t)(m0+rt)*Un + ncol;
                hf* o2 = sel==0? ch : ch2;
                *(__half2*)(o2+d0) = __floats2half2_rn(a[0], a[1]);
                *(__half2*)(o2+d0+(size_t)8*Un) = __floats2half2_rn(a[2], a[3]);
            } else {
                const int R = m0+rt, C = n0+ct;
                float2 v;
                v.x = a[0]+bias[C]; v.y = a[1]+bias[C+1];
                *(float2*)(cf+(size_t)R*Un+C) = v;
                v.x = a[2]+bias[C]; v.y = a[3]+bias[C+1];
                *(float2*)(cf+(size_t)(R+8)*Un+C) = v;
            }
        }
    }
}

// ---------------- fused flash attention + relative positions -----------------
#define PIT 144
#define AS_K    0
#define AS_V    9216
#define AS_PH   18432
#define AS_WR   36864       // fp16 128 x 132; aliased as Q staging during prologue
#define AS_QM   70656       // fp16 128 x 132 (computed in-kernel: Q . ek^T)
#define AS_MSK  104448      // fp32 1024, premultiplied by -1e9
#define AS_RM   108544      // fp32 128 : final row max
#define AS_TOT  109056

__global__ void __launch_bounds__(256,2) attn_fused(const float* __restrict__ maskg)
{
    extern __shared__ char smc[];
    const uint32_t S = smem_u32(smc);
    hf* swrh = (hf*)(smc + AS_WR);
    hf* sqm = (hf*)(smc + AS_QM);
    float* smk = (float*)(smc + AS_MSK);
    float* srm = (float*)(smc + AS_RM);
    const int t = threadIdx.x, lane = t&31, w = t>>5;
    const int bh = blockIdx.y, b = bh>>4, h = bh&15;
    const int i0 = blockIdx.x<<7;

    // Q tile 128x64 staged into WR region (not live yet)
    #pragma unroll
    for (int i=0;i<4;i++){
        int v = t + (i<<8);
        int r = v>>3, sg = v&7;
        const hf* src = g_qh + (((size_t)((b<<10)+i0+r))<<10) + (h<<6) + sg*8;
        cpa(S + AS_WR + r*PIT + sg*16, src, 16);
    }
    asm volatile("cp.async.commit_group;":::"memory");

    auto ldK = [&](int c){
        const int j0 = c<<6;
        #pragma unroll
        for (int i=0;i<2;i++){
            int e = t + (i<<8);
            int row = e>>3, sg = e&7;
            const hf* src = g_kh + (((size_t)((b<<10)+j0+row))<<10) + (h<<6) + sg*8;
            cpa(S + AS_K + row*PIT + sg*16, src, 16);
        }
        asm volatile("cp.async.commit_group;":::"memory");
    };
    auto ldV = [&](int c){
        const int j0 = c<<6;
        #pragma unroll
        for (int i=0;i<2;i++){
            int e = t + (i<<8);
            int row = e>>3, sg = e&7;
            const hf* src = g_vth + (((size_t)((bh<<6)+row))<<10) + j0 + sg*8;
            cpa(S + AS_V + row*PIT + sg*16, src, 16);
        }
        asm volatile("cp.async.commit_group;":::"memory");
    };
    auto ldEk = [&](int mc){
        #pragma unroll
        for (int i=0;i<2;i++){
            int e = t + (i<<8);
            int row = e>>3, sg = e&7;
            int m = (mc<<6) + row;
            int rs = m < MREL ? m : 0;
            const hf* src = g_ekh + ((size_t)h*MREL + rs)*Dn + sg*8;
            cpa(S + AS_K + row*PIT + sg*16, src, 16);
        }
        asm volatile("cp.async.commit_group;":::"memory");
    };
    auto ldEv = [&](int mc, uint32_t slot){
        #pragma unroll
        for (int i=0;i<2;i++){
            int e = t + (i<<8);
            int row = e>>3, sg = e&7;
            const hf* src = g_evth + (size_t)h*Dn*192 + (size_t)row*192 + (mc<<6) + sg*8;
            cpa(S + slot + row*PIT + sg*16, src, 16);
        }
        asm volatile("cp.async.commit_group;":::"memory");
    };

    for (int v=t; v<1024; v+=256) smk[v] = maskg[(b<<10)+v] * -1e9f;

    const int rA = lane&15, kA = (lane>>4)<<3;
    const int rB = (lane&7)+((lane>>4)<<3), kB = ((lane>>3)&1)<<3;
    const uint32_t aQ  = S + AS_WR + (16*w + rA)*PIT + kA*2;
    const uint32_t aPh = S + AS_PH + (16*w + rA)*PIT + kA*2;
    const uint32_t kK = S + AS_K;
    const uint32_t kV = S + AS_V;
    const int r0l = (w<<4) + (lane>>2), r1l = r0l + 8;
    const int cl0 = (lane&3)<<1;

    // ---- prologue: sqm = Q . ek^T ----
    asm volatile("cp.async.wait_group 0;":::"memory");
    __syncthreads();
    for (int mc=0; mc<3; mc++){
        ldEk(mc);
        asm volatile("cp.async.wait_group 0;":::"memory");
        __syncthreads();
        float s[8][4] = {};
        #pragma unroll
        for (int k16=0;k16<4;k16++){
            uint32_t ah4[4];
            ldsm4(ah4, aQ + k16*32);
            #pragma unroll
            for (int p4=0;p4<4;p4++){
                uint32_t bh4[4];
                ldsm4(bh4, kK + (p4*16 + rB)*PIT + kB*2 + k16*32);
                mma16816(s[2*p4],   ah4, bh4);
                mma16816(s[2*p4+1], ah4, bh4+2);
            }
        }
        #pragma unroll
        for (int ns=0;ns<8;ns++){
            int m = (mc<<6) + (ns<<3) + cl0;
            if (m <= 130){
                *(__half2*)(sqm + r0l*132 + m) = __floats2half2_rn(s[ns][0], s[ns][1]);
                *(__half2*)(sqm + r1l*132 + m) = __floats2half2_rn(s[ns][2], s[ns][3]);
            }
        }
        __syncthreads();
    }

    // ---- hoist Q fragments to registers; reuse staging smem as WR ----
    uint32_t q4[4][4];
    #pragma unroll
    for (int k16=0;k16<4;k16++) ldsm4(q4[k16], aQ + k16*32);
    __syncthreads();
    {
        const hf ninf = __float2half(-60000.f);
        for (int v=t; v<128*132; v+=256) swrh[v] = ninf;
    }
    __syncthreads();
    ldK(0); ldV(0);

    float o[8][4] = {};
    float M0 = -1e30f, M1 = -1e30f, L0 = 0.f, L1 = 0.f;
    float elo0 = 0.f, ehi0 = 0.f, elo1 = 0.f, ehi1 = 0.f;

    for (int c=0; c<16; c++){
        asm volatile("cp.async.wait_group 0;":::"memory");
        __syncthreads();

        // ---- S = Q K^T ----
        float s[8][4] = {};
        #pragma unroll
        for (int k16=0;k16<4;k16++){
            #pragma unroll
            for (int p4=0;p4<4;p4++){
                uint32_t bh4[4];
                ldsm4(bh4, kK + (p4*16 + rB)*PIT + kB*2 + k16*32);
                mma16816(s[2*p4],   q4[k16], bh4);
                mma16816(s[2*p4+1], q4[k16], bh4+2);
            }
        }
        __syncthreads();
        if (c+1 < 16) ldK(c+1);

        const int jbase = c<<6;
        const bool flo = (jbase <= i0 - 127);
        const bool fhi = (jbase >= i0 + 191);
        float mx0 = -1e30f, mx1 = -1e30f;
        float sum0 = 0.f, sum1 = 0.f;

        if (flo || fhi){
            const int qcol = flo ? 0 : 128;
            const float a0 = __half2float(sqm[r0l*132+qcol])*SCALE;
            const float a1 = __half2float(sqm[r1l*132+qcol])*SCALE;
            #pragma unroll
            for (int ns=0;ns<8;ns++){
                int jl = (ns<<3) + cl0;
                float mk0 = smk[jbase+jl], mk1 = smk[jbase+jl+1];
                s[ns][0] = s[ns][0]*SCALE + a0 + mk0;
                s[ns][1] = s[ns][1]*SCALE + a0 + mk1;
                s[ns][2] = s[ns][2]*SCALE + a1 + mk0;
                s[ns][3] = s[ns][3]*SCALE + a1 + mk1;
                mx0 = fmaxf(mx0, fmaxf(s[ns][0], s[ns][1]));
                mx1 = fmaxf(mx1, fmaxf(s[ns][2], s[ns][3]));
            }
            mx0 = fmaxf(mx0, __shfl_xor_sync(0xffffffffu, mx0, 1));
            mx0 = fmaxf(mx0, __shfl_xor_sync(0xffffffffu, mx0, 2));
            mx1 = fmaxf(mx1, __shfl_xor_sync(0xffffffffu, mx1, 1));
            mx1 = fmaxf(mx1, __shfl_xor_sync(0xffffffffu, mx1, 2));
            const float nM0 = fmaxf(M0, mx0), nM1 = fmaxf(M1, mx1);
            const float f0 = __expf(M0 - nM0), f1 = __expf(M1 - nM1);
            M0 = nM0; M1 = nM1;
            #pragma unroll
            for (int ns=0;ns<8;ns++){
                int jl = (ns<<3) + cl0;
                float p00=__expf(s[ns][0]-nM0), p01=__expf(s[ns][1]-nM0);
                float p10=__expf(s[ns][2]-nM1), p11=__expf(s[ns][3]-nM1);
                sum0 += p00+p01; sum1 += p10+p11;
                *(__half2*)(smc + AS_PH + r0l*PIT + jl*2) = __floats2half2_rn(p00, p01);
                *(__half2*)(smc + AS_PH + r1l*PIT + jl*2) = __floats2half2_rn(p10, p11);
            }
            #pragma unroll
            for (int ns=0;ns<8;ns++){ o[ns][0]*=f0; o[ns][1]*=f0; o[ns][2]*=f1; o[ns][3]*=f1; }
            L0 = L0*f0 + sum0;  L1 = L1*f1 + sum1;
            if (flo){ elo0 = elo0*f0 + sum0; elo1 = elo1*f1 + sum1;
                      ehi0 *= f0;            ehi1 *= f1; }
            else    { ehi0 = ehi0*f0 + sum0; ehi1 = ehi1*f1 + sum1;
                      elo0 *= f0;            elo1 *= f1; }
        } else {
            #pragma unroll
            for (int ns=0;ns<8;ns++){
                int jl = (ns<<3) + cl0;
                int jg0 = jbase + jl, jg1 = jg0 + 1;
                int d00 = jg0-(i0+r0l); int c00 = d00<-64?-64:(d00>64?64:d00);
                int d01 = jg1-(i0+r0l); int c01 = d01<-64?-64:(d01>64?64:d01);
                int d10 = jg0-(i0+r1l); int c10 = d10<-64?-64:(d10>64?64:d10);
                int d11 = jg1-(i0+r1l); int c11 = d11<-64?-64:(d11>64?64:d11);
                s[ns][0] = (s[ns][0] + __half2float(sqm[r0l*132+c00+64]))*SCALE + smk[jg0];
                s[ns][1] = (s[ns][1] + __half2float(sqm[r0l*132+c01+64]))*SCALE + smk[jg1];
                s[ns][2] = (s[ns][2] + __half2float(sqm[r1l*132+c10+64]))*SCALE + smk[jg0];
                s[ns][3] = (s[ns][3] + __half2float(sqm[r1l*132+c11+64]))*SCALE + smk[jg1];
                if (d00>-64 && d00<64) swrh[r0l*132+d00+64] = __float2half(s[ns][0]);
                if (d01>-64 && d01<64) swrh[r0l*132+d01+64] = __float2half(s[ns][1]);
                if (d10>-64 && d10<64) swrh[r1l*132+d10+64] = __float2half(s[ns][2]);
                if (d11>-64 && d11<64) swrh[r1l*132+d11+64] = __float2half(s[ns][3]);
                mx0 = fmaxf(mx0, fmaxf(s[ns][0], s[ns][1]));
                mx1 = fmaxf(mx1, fmaxf(s[ns][2], s[ns][3]));
            }
            mx0 = fmaxf(mx0, __shfl_xor_sync(0xffffffffu, mx0, 1));
            mx0 = fmaxf(mx0, __shfl_xor_sync(0xffffffffu, mx0, 2));
            mx1 = fmaxf(mx1, __shfl_xor_sync(0xffffffffu, mx1, 1));
            mx1 = fmaxf(mx1, __shfl_xor_sync(0xffffffffu, mx1, 2));
            const float nM0 = fmaxf(M0, mx0), nM1 = fmaxf(M1, mx1);
            const float f0 = __expf(M0 - nM0), f1 = __expf(M1 - nM1);
            M0 = nM0; M1 = nM1;

            float ce0 = 0.f, ch0 = 0.f, ce1 = 0.f, ch1 = 0.f;
            #pragma unroll
            for (int ns=0;ns<8;ns++){
                int jl = (ns<<3) + cl0;
                int jg0 = jbase + jl, jg1 = jg0 + 1;
                int d00 = jg0-(i0+r0l), d01 = jg1-(i0+r0l);
                int d10 = jg0-(i0+r1l), d11 = jg1-(i0+r1l);
                float p00=__expf(s[ns][0]-nM0), p01=__expf(s[ns][1]-nM0);
                float p10=__expf(s[ns][2]-nM1), p11=__expf(s[ns][3]-nM1);
                sum0 += p00+p01; sum1 += p10+p11;
                if (d00<=-64) ce0+=p00; else if (d00>=64) ch0+=p00;
                if (d01<=-64) ce0+=p01; else if (d01>=64) ch0+=p01;
                if (d10<=-64) ce1+=p10; else if (d10>=64) ch1+=p10;
                if (d11<=-64) ce1+=p11; else if (d11>=64) ch1+=p11;
                *(__half2*)(smc + AS_PH + r0l*PIT + jl*2) = __floats2half2_rn(p00, p01);
                *(__half2*)(smc + AS_PH + r1l*PIT + jl*2) = __floats2half2_rn(p10, p11);
            }
            #pragma unroll
            for (int ns=0;ns<8;ns++){ o[ns][0]*=f0; o[ns][1]*=f0; o[ns][2]*=f1; o[ns][3]*=f1; }
            L0 = L0*f0 + sum0;  L1 = L1*f1 + sum1;
            elo0 = elo0*f0 + ce0; ehi0 = ehi0*f0 + ch0;
            elo1 = elo1*f1 + ce1; ehi1 = ehi1*f1 + ch1;
        }
        __syncwarp();

        // ---- O += P V^T ----
        #pragma unroll
        for (int k16=0;k16<4;k16++){
            uint32_t ph4[4];
            ldsm4(ph4, aPh + k16*32);
            #pragma unroll
            for (int p4=0;p4<4;p4++){
                uint32_t vh4[4];
                ldsm4(vh4, kV + (p4*16 + rB)*PIT + kB*2 + k16*32);
                mma16816(o[2*p4],   ph4, vh4);
                mma16816(o[2*p4+1], ph4, vh4+2);
            }
        }
        __syncthreads();
        if (c+1 < 16) ldV(c+1);
    }

    // finalize row state
    elo0 += __shfl_xor_sync(0xffffffffu, elo0, 1); elo0 += __shfl_xor_sync(0xffffffffu, elo0, 2);
    ehi0 += __shfl_xor_sync(0xffffffffu, ehi0, 1); ehi0 += __shfl_xor_sync(0xffffffffu, ehi0, 2);
    elo1 += __shfl_xor_sync(0xffffffffu, elo1, 1); elo1 += __shfl_xor_sync(0xffffffffu, elo1, 2);
    ehi1 += __shfl_xor_sync(0xffffffffu, ehi1, 1); ehi1 += __shfl_xor_sync(0xffffffffu, ehi1, 2);
    L0 += __shfl_xor_sync(0xffffffffu, L0, 1); L0 += __shfl_xor_sync(0xffffffffu, L0, 2);
    L1 += __shfl_xor_sync(0xffffffffu, L1, 1); L1 += __shfl_xor_sync(0xffffffffu, L1, 2);
    if ((lane&3)==0){
        swrh[r0l*132+0]   = __float2half(elo0);
        swrh[r0l*132+128] = __float2half(ehi0);
        swrh[r1l*132+0]   = __float2half(elo1);
        swrh[r1l*132+128] = __float2half(ehi1);
        srm[r0l] = M0; srm[r1l] = M1;
    }
    __syncthreads();

    // ---- O += wr @ ev^T (3 chunks, double-buffered across K/V slots) ----
    ldEv(0, AS_V);
    for (int mc=0; mc<3; mc++){
        for (int idx=t; idx<128*64; idx+=256){
            int r = idx>>6, c2 = idx&63;
            int col = (mc<<6) + c2;
            float v;
            if (col==0 || col==128) v = __half2float(swrh[r*132+col]);
            else if (col < MREL)    v = __expf(__half2float(swrh[r*132+col]) - srm[r]);
            else                    v = 0.f;
            *(hf*)(smc + AS_PH + r*PIT + c2*2) = __float2half(v);
        }
        asm volatile("cp.async.wait_group 0;":::"memory");
        __syncthreads();
        if (mc < 2) ldEv(mc+1, (mc&1)? AS_V : AS_K);
        const uint32_t slot = (mc&1)? kK : kV;
        #pragma unroll
        for (int k16=0;k16<4;k16++){
            uint32_t ph4[4];
            ldsm4(ph4, aPh + k16*32);
            #pragma unroll
            for (int p4=0;p4<4;p4++){
                uint32_t vh4[4];
                ldsm4(vh4, slot + (p4*16 + rB)*PIT + kB*2 + k16*32);
                mma16816(o[2*p4],   ph4, vh4);
                mma16816(o[2*p4+1], ph4, vh4+2);
            }
        }
        __syncthreads();
    }

    // ---- normalize + emit ----
    const float inv0 = 1.0f/L0, inv1 = 1.0f/L1;
    #pragma unroll
    for (int ns=0;ns<8;ns++){
        int ct = (ns<<3) + cl0;
        size_t d0 = ((size_t)((b<<10)+i0+r0l)<<10) + (h<<6) + ct;
        size_t d1 = ((size_t)((b<<10)+i0+r1l)<<10) + (h<<6) + ct;
        *(__half2*)(g_oh+d0) = __floats2half2_rn(o[ns][0]*inv0, o[ns][1]*inv0);
        *(__half2*)(g_oh+d1) = __floats2half2_rn(o[ns][2]*inv1, o[ns][3]*inv1);
    }
}

// ---------------- fused prep kernel ------------------------------------------
// blocks [0,4096): weight transpose (z = id>>10); [4096,8192): x convert;
// [8192,8224): ek/ev prep.
__global__ void prep_all(const float* __restrict__ x,
                         const float* __restrict__ w0, const float* __restrict__ w1,
                         const float* __restrict__ w2, const float* __restrict__ w3,
                         const float* __restrict__ ek, const float* __restrict__ ev)
{
    __shared__ float tl[32][33];
    const int id = blockIdx.x;
    const int t = threadIdx.x;

    if (id < 4096){
        const int z = id >> 10, rem = id & 1023;
        const int bx = rem & 31, by = rem >> 5;
        const float* w = z==0? w0 : (z==1? w1 : (z==2? w2 : w3));
        hf* oh = g_wth + (size_t)z*Un*Un;
        const int n0 = bx*32, k0 = by*32;
        const int tx = t & 31, ty = t >> 5;        // (32,8)
        for (int yy = 0; yy < 32; yy += 8)
            tl[ty+yy][tx] = w[(size_t)(k0+ty+yy)*Un + n0+tx];
        __syncthreads();
        for (int yy = 0; yy < 32; yy += 8)
            oh[(size_t)(n0+ty+yy)*Un + k0+tx] = __float2half(tl[tx][ty+yy]);
    } else if (id < 8192){
        int i = (id-4096)*256 + t;                 // float4 index
        float4 v = ((const float4*)x)[i];
        hf hb[4];
        hb[0]=__float2half(v.x); hb[1]=__float2half(v.y);
        hb[2]=__float2half(v.z); hb[3]=__float2half(v.w);
        ((uint2*)g_xh)[i] = *(uint2*)hb;
    } else {
        const int e = id - 8192;
        const int hh = e >> 1;
        if ((e & 1) == 0){
            for (int v = t; v < Dn*192; v += 256){
                int d = v/192, m = v%192;
                float f = (m < MREL) ? ev[(size_t)hh*MREL*Dn + (size_t)m*Dn + d] : 0.f;
                g_evth[(size_t)hh*Dn*192 + v] = __float2half(f);
            }
        } else {
            for (int v = t; v < MREL*Dn; v += 256)
                g_ekh[(size_t)hh*MREL*Dn + v] = __float2half(ek[(size_t)hh*MREL*Dn + v]);
        }
    }
}

// -----------------------------------------------------------------------------
#define SMEMG (2*2*128*144)    // 73728 (2-stage, measured best)

extern "C" void kernel_launch(void* const* d_in, const int* in_sizes, int n_in,
                              void* d_out, int out_size)
{
    const float* x    = (const float*)d_in[0];
    const float* mask = (const float*)d_in[1];
    const float* wq   = (const float*)d_in[2];
    const float* wk   = (const float*)d_in[3];
    const float* wv   = (const float*)d_in[4];
    const float* wo   = (const float*)d_in[5];
    const float* bo   = (const float*)d_in[6];
    const float* ek   = (const float*)d_in[7];
    const float* ev   = (const float*)d_in[8];
    float* out = (float*)d_out;

    hf *xh,*wth,*qh,*kh,*oh;
    cudaGetSymbolAddress((void**)&xh, g_xh);
    cudaGetSymbolAddress((void**)&wth, g_wth);
    cudaGetSymbolAddress((void**)&qh, g_qh);
    cudaGetSymbolAddress((void**)&kh, g_kh);
    cudaGetSymbolAddress((void**)&oh, g_oh);

    cudaFuncSetAttribute(gemm_mma<128,5,16>, cudaFuncAttributeMaxDynamicSharedMemorySize, SMEMG);
    cudaFuncSetAttribute(gemm_mma<128,4,16>, cudaFuncAttributeMaxDynamicSharedMemorySize, SMEMG);
    cudaFuncSetAttribute(attn_fused, cudaFuncAttributeMaxDynamicSharedMemorySize, AS_TOT);

    // fused prep: x convert + weight transposes + ek/ev prep (one launch)
    prep_all<<<8224, 256>>>(x, wq, wk, wv, wo, ek, ev);

    // fused Q|K|V projection (K-chunks of 64, 2-stage, single barrier per chunk)
    gemm_mma<128,5,16><<<dim3(24, (Bn*Ln)/128, 1),256,SMEMG>>>(
        xh, wth, 0, qh, kh, 0);

    // fused attention (qm + logits + softmax + rel-value + AV), 2 CTA/SM
    attn_fused<<<dim3(Ln/128, BHn), 256, AS_TOT>>>(mask);

    // out = O @ Wo^T + bo
    gemm_mma<128,4,16><<<dim3(8, (Bn*Ln)/128, 1),256,SMEMG>>>(
        oh, wth+3*Un*Un, out, 0, 0, bo);
}